// round 1
// baseline (speedup 1.0000x reference)
#include <cuda_runtime.h>

#define NQ 4
#define NL 8
#define NGATES ((NL + 1) * NQ)   // 36 fused RZ*RY*RX gates

// Precomputed fused single-qubit gates: per gate 8 floats
// U00r,U00i,U01r,U01i,U10r,U10i,U11r,U11i
__device__ float g_gates[NGATES * 8];

__global__ void precompute_gates_kernel(const float* __restrict__ theta) {
    int g = blockIdx.x * blockDim.x + threadIdx.x;
    if (g >= NGATES) return;
    float a = theta[g * 3 + 0];
    float b = theta[g * 3 + 1];
    float c = theta[g * 3 + 2];
    float sa, ca, sb, cb, sc, cc;
    sincosf(0.5f * a, &sa, &ca);
    sincosf(0.5f * b, &sb, &cb);
    sincosf(0.5f * c, &sc, &cc);
    // M = Ry(b) * Rx(a):
    // M00 = cb*ca + i*sb*sa   M01 = -sb*ca - i*cb*sa
    // M10 = sb*ca - i*cb*sa   M11 =  cb*ca - i*sb*sa
    float m00r = cb * ca, m00i =  sb * sa;
    float m01r = -sb * ca, m01i = -cb * sa;
    float m10r =  sb * ca, m10i = -cb * sa;
    float m11r =  cb * ca, m11i = -sb * sa;
    // U = Rz(c) * M : row0 *= (cc - i*sc), row1 *= (cc + i*sc)
    float u00r = m00r * cc + m00i * sc, u00i = m00i * cc - m00r * sc;
    float u01r = m01r * cc + m01i * sc, u01i = m01i * cc - m01r * sc;
    float u10r = m10r * cc - m10i * sc, u10i = m10i * cc + m10r * sc;
    float u11r = m11r * cc - m11i * sc, u11i = m11i * cc + m11r * sc;
    float* o = &g_gates[g * 8];
    o[0] = u00r; o[1] = u00i; o[2] = u01r; o[3] = u01i;
    o[4] = u10r; o[5] = u10i; o[6] = u11r; o[7] = u11i;
}

__global__ __launch_bounds__(256)
void pqc_kernel(const float4* __restrict__ x,
                const float* __restrict__ lmbd,
                float* __restrict__ out, int B) {
    __shared__ float sh_g[NGATES * 8];
    __shared__ float sh_l[NL * NQ];
    for (int i = threadIdx.x; i < NGATES * 8; i += blockDim.x) sh_g[i] = g_gates[i];
    for (int i = threadIdx.x; i < NL * NQ; i += blockDim.x) sh_l[i] = lmbd[i];
    __syncthreads();

    int t = blockIdx.x * blockDim.x + threadIdx.x;
    if (t >= B) return;

    float4 xv = x[t];
    float xq[NQ] = {xv.x, xv.y, xv.z, xv.w};

    // state: flat index i = b0*8 + b1*4 + b2*2 + b3, qubit q stride = 8>>q
    float sr[16], si[16];
#pragma unroll
    for (int i = 0; i < 16; i++) { sr[i] = 0.0f; si[i] = 0.0f; }
    sr[0] = 1.0f;

    for (int l = 0; l < NL; l++) {
        const float* gl = &sh_g[l * NQ * 8];
        // --- fixed fused RZ*RY*RX gates ---
#pragma unroll
        for (int q = 0; q < NQ; q++) {
            float u00r = gl[q * 8 + 0], u00i = gl[q * 8 + 1];
            float u01r = gl[q * 8 + 2], u01i = gl[q * 8 + 3];
            float u10r = gl[q * 8 + 4], u10i = gl[q * 8 + 5];
            float u11r = gl[q * 8 + 6], u11i = gl[q * 8 + 7];
            const int stride = 8 >> q;
#pragma unroll
            for (int i = 0; i < 16; i++) {
                if (i & stride) continue;
                const int j = i + stride;
                float ar = sr[i], ai = si[i], br = sr[j], bi = si[j];
                sr[i] = u00r * ar - u00i * ai + u01r * br - u01i * bi;
                si[i] = u00r * ai + u00i * ar + u01r * bi + u01i * br;
                sr[j] = u10r * ar - u10i * ai + u11r * br - u11i * bi;
                si[j] = u10r * ai + u10i * ar + u11r * bi + u11i * br;
            }
        }
        // --- CZ ring (0,1),(1,2),(2,3),(3,0): combined fixed sign per index ---
#pragma unroll
        for (int i = 0; i < 16; i++) {
            const int b0 = (i >> 3) & 1, b1 = (i >> 2) & 1, b2 = (i >> 1) & 1, b3 = i & 1;
            const int p = (b0 & b1) ^ (b1 & b2) ^ (b2 & b3) ^ (b3 & b0);
            if (p) { sr[i] = -sr[i]; si[i] = -si[i]; }
        }
        // --- per-sample RX(lmbd * x) ---
#pragma unroll
        for (int q = 0; q < NQ; q++) {
            float ang = 0.5f * sh_l[l * NQ + q] * xq[q];
            float s, c;
            __sincosf(ang, &s, &c);
            const int stride = 8 >> q;
#pragma unroll
            for (int i = 0; i < 16; i++) {
                if (i & stride) continue;
                const int j = i + stride;
                float ar = sr[i], ai = si[i], br = sr[j], bi = si[j];
                sr[i] =  c * ar + s * bi;
                si[i] =  c * ai - s * br;
                sr[j] =  s * ai + c * br;
                si[j] = -s * ar + c * bi;
            }
        }
    }

    // --- final fixed gate layer (params[NL]) ---
    {
        const float* gl = &sh_g[NL * NQ * 8];
#pragma unroll
        for (int q = 0; q < NQ; q++) {
            float u00r = gl[q * 8 + 0], u00i = gl[q * 8 + 1];
            float u01r = gl[q * 8 + 2], u01i = gl[q * 8 + 3];
            float u10r = gl[q * 8 + 4], u10i = gl[q * 8 + 5];
            float u11r = gl[q * 8 + 6], u11i = gl[q * 8 + 7];
            const int stride = 8 >> q;
#pragma unroll
            for (int i = 0; i < 16; i++) {
                if (i & stride) continue;
                const int j = i + stride;
                float ar = sr[i], ai = si[i], br = sr[j], bi = si[j];
                sr[i] = u00r * ar - u00i * ai + u01r * br - u01i * bi;
                si[i] = u00r * ai + u00i * ar + u01r * bi + u01i * br;
                sr[j] = u10r * ar - u10i * ai + u11r * br - u11i * bi;
                si[j] = u10r * ai + u10i * ar + u11r * bi + u11i * br;
            }
        }
    }

    // --- <Z0 Z1 Z2 Z3> ---
    float e = 0.0f;
#pragma unroll
    for (int i = 0; i < 16; i++) {
        const int b0 = (i >> 3) & 1, b1 = (i >> 2) & 1, b2 = (i >> 1) & 1, b3 = i & 1;
        const float par = ((b0 ^ b1 ^ b2 ^ b3) & 1) ? -1.0f : 1.0f;
        float p = sr[i] * sr[i] + si[i] * si[i];
        e += par * p;
    }
    out[t] = e;
}

extern "C" void kernel_launch(void* const* d_in, const int* in_sizes, int n_in,
                              void* d_out, int out_size) {
    const float* x     = (const float*)d_in[0];   // [B, 4]
    const float* theta = (const float*)d_in[1];   // [1, 108]
    const float* lmbd  = (const float*)d_in[2];   // [32]
    float* out = (float*)d_out;                   // [B, 1]
    int B = in_sizes[0] / NQ;

    precompute_gates_kernel<<<1, 64>>>(theta);
    int threads = 256;
    int blocks = (B + threads - 1) / threads;
    pqc_kernel<<<blocks, threads>>>((const float4*)x, lmbd, out, B);
}

// round 2
// speedup vs baseline: 1.2895x; 1.2895x over previous
#include <cuda_runtime.h>

#define NQ 4
#define NL 8
#define NGATES ((NL + 1) * NQ)

typedef unsigned long long ull;

// ---------- packed f32x2 helpers (Blackwell FFMA2 path) ----------
__device__ __forceinline__ ull pk2(float lo, float hi) {
    ull r; asm("mov.b64 %0, {%1,%2};" : "=l"(r) : "f"(lo), "f"(hi)); return r;
}
__device__ __forceinline__ ull bc2(float x) { return pk2(x, x); }
__device__ __forceinline__ void up2(ull v, float& lo, float& hi) {
    asm("mov.b64 {%0,%1}, %2;" : "=f"(lo), "=f"(hi) : "l"(v));
}
__device__ __forceinline__ ull fma2(ull a, ull b, ull c) {
    ull d; asm("fma.rn.f32x2 %0, %1, %2, %3;" : "=l"(d) : "l"(a), "l"(b), "l"(c)); return d;
}
__device__ __forceinline__ ull mul2(ull a, ull b) {
    ull d; asm("mul.rn.f32x2 %0, %1, %2;" : "=l"(d) : "l"(a), "l"(b)); return d;
}
__device__ __forceinline__ ull swap2(ull v) { float l, h; up2(v, l, h); return pk2(h, l); }

// Precomputed fused U = RZ*RY*RX gates: 8 floats each
// [U00r,U00i,U01r,U01i,U10r,U10i,U11r,U11i]
__device__ float g_gates[NGATES * 8];

__global__ void precompute_gates_kernel(const float* __restrict__ theta) {
    int g = blockIdx.x * blockDim.x + threadIdx.x;
    if (g >= NGATES) return;
    float a = theta[g * 3 + 0];
    float b = theta[g * 3 + 1];
    float c = theta[g * 3 + 2];
    float sa, ca, sb, cb, sc, cc;
    sincosf(0.5f * a, &sa, &ca);
    sincosf(0.5f * b, &sb, &cb);
    sincosf(0.5f * c, &sc, &cc);
    // M = Ry(b)*Rx(a)
    float m00r = cb * ca, m00i =  sb * sa;
    float m01r = -sb * ca, m01i = -cb * sa;
    float m10r =  sb * ca, m10i = -cb * sa;
    float m11r =  cb * ca, m11i = -sb * sa;
    // U = Rz(c)*M
    float* o = &g_gates[g * 8];
    o[0] = m00r * cc + m00i * sc; o[1] = m00i * cc - m00r * sc;
    o[2] = m01r * cc + m01i * sc; o[3] = m01i * cc - m01r * sc;
    o[4] = m10r * cc - m10i * sc; o[5] = m10i * cc + m10r * sc;
    o[6] = m11r * cc - m11i * sc; o[7] = m11i * cc + m11r * sc;
}

// Apply a 2x2 complex gate (packs p??r/p??i/n??i in scope) to slot pair (k,j)
#define APPLY(k, j) { \
    ull t0r = fma2(n01i, I[j], fma2(p01r, R[j], fma2(n00i, I[k], mul2(p00r, R[k])))); \
    ull t0i = fma2(p01i, R[j], fma2(p01r, I[j], fma2(p00i, R[k], mul2(p00r, I[k])))); \
    ull t1r = fma2(n11i, I[j], fma2(p11r, R[j], fma2(n10i, I[k], mul2(p10r, R[k])))); \
    ull t1i = fma2(p11i, R[j], fma2(p11r, I[j], fma2(p10i, R[k], mul2(p10r, I[k])))); \
    R[k] = t0r; I[k] = t0i; R[j] = t1r; I[j] = t1i; }

__global__ __launch_bounds__(256)
void pqc_kernel(const float4* __restrict__ x,
                const float* __restrict__ lmbd,
                float* __restrict__ out, int B) {
    __shared__ float sh_g[NGATES * 8];
    __shared__ float sh_l[NL * NQ];
    for (int i = threadIdx.x; i < NGATES * 8; i += blockDim.x) sh_g[i] = g_gates[i];
    for (int i = threadIdx.x; i < NL * NQ; i += blockDim.x) sh_l[i] = 0.5f * lmbd[i];
    __syncthreads();

    int t = blockIdx.x * blockDim.x + threadIdx.x;
    if (t >= B) return;

    float4 xv = x[t];
    float xq[NQ] = {xv.x, xv.y, xv.z, xv.w};

    // Packed state: slot k (k = b1*4+b2*2+b3) holds lanes (amp[k], amp[k+8]) i.e. b0=0/1
    ull R[8], I[8];

    // ---- layer-0 fixed gates on |0000> : tensor product of gate column 0 ----
    {
        float q1r[2], q1i[2], q2r[2], q2i[2], q3r[2], q3i[2];
        q1r[0] = sh_g[8 + 0];  q1i[0] = sh_g[8 + 1];  q1r[1] = sh_g[8 + 4];  q1i[1] = sh_g[8 + 5];
        q2r[0] = sh_g[16 + 0]; q2i[0] = sh_g[16 + 1]; q2r[1] = sh_g[16 + 4]; q2i[1] = sh_g[16 + 5];
        q3r[0] = sh_g[24 + 0]; q3i[0] = sh_g[24 + 1]; q3r[1] = sh_g[24 + 4]; q3i[1] = sh_g[24 + 5];
        float a0r = sh_g[0], a0i = sh_g[1], a1r = sh_g[4], a1i = sh_g[5];
        ull Apr = pk2(a0r, a1r), Api = pk2(a0i, a1i), nApi = pk2(-a0i, -a1i);
        float wr[4], wi[4];
#pragma unroll
        for (int b2 = 0; b2 < 2; b2++)
#pragma unroll
            for (int b3 = 0; b3 < 2; b3++) {
                wr[b2 * 2 + b3] = q2r[b2] * q3r[b3] - q2i[b2] * q3i[b3];
                wi[b2 * 2 + b3] = q2r[b2] * q3i[b3] + q2i[b2] * q3r[b3];
            }
#pragma unroll
        for (int k = 0; k < 8; k++) {
            int b1 = k >> 2, w = k & 3;
            float vr = q1r[b1] * wr[w] - q1i[b1] * wi[w];
            float vi = q1r[b1] * wi[w] + q1i[b1] * wr[w];
            ull vbr = bc2(vr), vbi = bc2(vi);
            R[k] = fma2(nApi, vbi, mul2(Apr, vbr));
            I[k] = fma2(Api, vbr, mul2(Apr, vbi));
        }
    }

    // CZ sign masks (packed lanes b0=0,b0=1): slots 1,4 -> (+,-); slots 3,6 -> (-,+)
    const ull PN = 0xBF8000003F800000ULL;  // (lo=+1, hi=-1)
    const ull NP = 0x3F800000BF800000ULL;  // (lo=-1, hi=+1)

    for (int l = 0; l < NL; l++) {
        // ---- CZ ring ----
        R[1] = mul2(R[1], PN); I[1] = mul2(I[1], PN);
        R[4] = mul2(R[4], PN); I[4] = mul2(I[4], PN);
        R[3] = mul2(R[3], NP); I[3] = mul2(I[3], NP);
        R[6] = mul2(R[6], NP); I[6] = mul2(I[6], NP);

        const float* gl = &sh_g[(l + 1) * NQ * 8];
        const float* ll = &sh_l[l * NQ];

        // ---- per qubit: V = U(l+1,q) * RX(lmbd*x) , build then apply ----
#pragma unroll
        for (int q = 0; q < NQ; q++) {
            float s, c;
            __sincosf(ll[q] * xq[q], &s, &c);
            const float* u = gl + q * 8;
            float v0 = c * u[0] + s * u[3];  // V00r
            float v1 = c * u[1] - s * u[2];  // V00i
            float v2 = s * u[1] + c * u[2];  // V01r
            float v3 = c * u[3] - s * u[0];  // V01i
            float v4 = c * u[4] + s * u[7];  // V10r
            float v5 = c * u[5] - s * u[6];  // V10i
            float v6 = s * u[5] + c * u[6];  // V11r
            float v7 = c * u[7] - s * u[4];  // V11i

            if (q == 0) {
                // intra-register qubit: lanes are the (k, k+8) pair
                ull Ar = pk2(v0, v6), Ai = pk2(v1, v7), nAi = pk2(-v1, -v7);
                ull Br = pk2(v2, v4), Bi = pk2(v3, v5), nBi = pk2(-v3, -v5);
#pragma unroll
                for (int k = 0; k < 8; k++) {
                    ull Rs = swap2(R[k]), Is = swap2(I[k]);
                    ull nr = fma2(nBi, Is, fma2(Br, Rs, fma2(nAi, I[k], mul2(Ar, R[k]))));
                    ull ni = fma2(Bi, Rs, fma2(Br, Is, fma2(Ai, R[k], mul2(Ar, I[k]))));
                    R[k] = nr; I[k] = ni;
                }
            } else {
                ull p00r = bc2(v0), p00i = bc2(v1), n00i = bc2(-v1);
                ull p01r = bc2(v2), p01i = bc2(v3), n01i = bc2(-v3);
                ull p10r = bc2(v4), p10i = bc2(v5), n10i = bc2(-v5);
                ull p11r = bc2(v6), p11i = bc2(v7), n11i = bc2(-v7);
                if (q == 1)      { APPLY(0, 4) APPLY(1, 5) APPLY(2, 6) APPLY(3, 7) }
                else if (q == 2) { APPLY(0, 2) APPLY(1, 3) APPLY(4, 6) APPLY(5, 7) }
                else             { APPLY(0, 1) APPLY(2, 3) APPLY(4, 5) APPLY(6, 7) }
            }
        }
    }

    // ---- <Z0 Z1 Z2 Z3> ----
    // slot popcount even {0,3,5,6}: lane parity (+,-) ; odd {1,2,4,7}: (-,+)
    ull accA = 0, accB = 0;
#pragma unroll
    for (int k = 0; k < 8; k++) {
        bool even = (k == 0 || k == 3 || k == 5 || k == 6);
        if (even) { accA = fma2(R[k], R[k], accA); accA = fma2(I[k], I[k], accA); }
        else      { accB = fma2(R[k], R[k], accB); accB = fma2(I[k], I[k], accB); }
    }
    float aL, aH, bL, bH;
    up2(accA, aL, aH); up2(accB, bL, bH);
    out[t] = (aL - aH) - (bL - bH);
}

extern "C" void kernel_launch(void* const* d_in, const int* in_sizes, int n_in,
                              void* d_out, int out_size) {
    const float* x     = (const float*)d_in[0];   // [B, 4]
    const float* theta = (const float*)d_in[1];   // [1, 108]
    const float* lmbd  = (const float*)d_in[2];   // [32]
    float* out = (float*)d_out;                   // [B, 1]
    int B = in_sizes[0] / NQ;

    precompute_gates_kernel<<<1, 64>>>(theta);
    int threads = 256;
    int blocks = (B + threads - 1) / threads;
    pqc_kernel<<<blocks, threads>>>((const float4*)x, lmbd, out, B);
}

// round 4
// speedup vs baseline: 1.3240x; 1.0267x over previous
#include <cuda_runtime.h>

#define NQ 4
#define NL 8
#define NGATES ((NL + 1) * NQ)

typedef unsigned long long ull;

// ---------- packed f32x2 helpers (Blackwell FFMA2 path) ----------
__device__ __forceinline__ ull pk2(float lo, float hi) {
    ull r; asm("mov.b64 %0, {%1,%2};" : "=l"(r) : "f"(lo), "f"(hi)); return r;
}
__device__ __forceinline__ ull bc2(float x) { return pk2(x, x); }
__device__ __forceinline__ void up2(ull v, float& lo, float& hi) {
    asm("mov.b64 {%0,%1}, %2;" : "=f"(lo), "=f"(hi) : "l"(v));
}
__device__ __forceinline__ ull fma2(ull a, ull b, ull c) {
    ull d; asm("fma.rn.f32x2 %0, %1, %2, %3;" : "=l"(d) : "l"(a), "l"(b), "l"(c)); return d;
}
__device__ __forceinline__ ull mul2(ull a, ull b) {
    ull d; asm("mul.rn.f32x2 %0, %1, %2;" : "=l"(d) : "l"(a), "l"(b)); return d;
}
__device__ __forceinline__ ull swap2(ull v) { float l, h; up2(v, l, h); return pk2(h, l); }

// Precomputed fused U = RZ*RY*RX gates: 8 floats each
__device__ float g_gates[NGATES * 8];

__global__ void precompute_gates_kernel(const float* __restrict__ theta) {
    int g = blockIdx.x * blockDim.x + threadIdx.x;
    if (g >= NGATES) return;
    float a = theta[g * 3 + 0];
    float b = theta[g * 3 + 1];
    float c = theta[g * 3 + 2];
    float sa, ca, sb, cb, sc, cc;
    sincosf(0.5f * a, &sa, &ca);
    sincosf(0.5f * b, &sb, &cb);
    sincosf(0.5f * c, &sc, &cc);
    float m00r = cb * ca, m00i =  sb * sa;
    float m01r = -sb * ca, m01i = -cb * sa;
    float m10r =  sb * ca, m10i = -cb * sa;
    float m11r =  cb * ca, m11i = -sb * sa;
    float* o = &g_gates[g * 8];
    o[0] = m00r * cc + m00i * sc; o[1] = m00i * cc - m00r * sc;
    o[2] = m01r * cc + m01i * sc; o[3] = m01i * cc - m01r * sc;
    o[4] = m10r * cc - m10i * sc; o[5] = m10i * cc + m10r * sc;
    o[6] = m11r * cc - m11i * sc; o[7] = m11i * cc + m11r * sc;
}

struct G2 {
    ull p00r, p00i, n00i, p01r, p01i, n01i;
    ull p10r, p10i, n10i, p11r, p11i, n11i;
};

__device__ __forceinline__ void mkG(G2& g, const float v[8]) {
    g.p00r = bc2(v[0]); g.p00i = bc2(v[1]); g.n00i = bc2(-v[1]);
    g.p01r = bc2(v[2]); g.p01i = bc2(v[3]); g.n01i = bc2(-v[3]);
    g.p10r = bc2(v[4]); g.p10i = bc2(v[5]); g.n10i = bc2(-v[5]);
    g.p11r = bc2(v[6]); g.p11i = bc2(v[7]); g.n11i = bc2(-v[7]);
}

__device__ __forceinline__ void app(ull* R, ull* I, int k, int j, const G2& g) {
    ull t0r = fma2(g.n01i, I[j], fma2(g.p01r, R[j], fma2(g.n00i, I[k], mul2(g.p00r, R[k]))));
    ull t0i = fma2(g.p01i, R[j], fma2(g.p01r, I[j], fma2(g.p00i, R[k], mul2(g.p00r, I[k]))));
    ull t1r = fma2(g.n11i, I[j], fma2(g.p11r, R[j], fma2(g.n10i, I[k], mul2(g.p10r, R[k]))));
    ull t1i = fma2(g.p11i, R[j], fma2(g.p11r, I[j], fma2(g.p10i, R[k], mul2(g.p10r, I[k]))));
    R[k] = t0r; I[k] = t0i; R[j] = t1r; I[j] = t1i;
}

// Apply 2x2 gate v[8] on qubit Q to packed state (R,I). Slot k packs amps (k, k+8).
template <int Q>
__device__ __forceinline__ void apply_q(ull* R, ull* I, const float v[8]) {
    if (Q == 0) {
        ull Ar = pk2(v[0], v[6]), Ai = pk2(v[1], v[7]), nAi = pk2(-v[1], -v[7]);
        ull Br = pk2(v[2], v[4]), Bi = pk2(v[3], v[5]), nBi = pk2(-v[3], -v[5]);
#pragma unroll
        for (int k = 0; k < 8; k++) {
            ull Rs = swap2(R[k]), Is = swap2(I[k]);
            ull nr = fma2(nBi, Is, fma2(Br, Rs, fma2(nAi, I[k], mul2(Ar, R[k]))));
            ull ni = fma2(Bi, Rs, fma2(Br, Is, fma2(Ai, R[k], mul2(Ar, I[k]))));
            R[k] = nr; I[k] = ni;
        }
    } else {
        G2 g; mkG(g, v);
        if (Q == 1)      { app(R, I, 0, 4, g); app(R, I, 1, 5, g); app(R, I, 2, 6, g); app(R, I, 3, 7, g); }
        else if (Q == 2) { app(R, I, 0, 2, g); app(R, I, 1, 3, g); app(R, I, 4, 6, g); app(R, I, 5, 7, g); }
        else             { app(R, I, 0, 1, g); app(R, I, 2, 3, g); app(R, I, 4, 5, g); app(R, I, 6, 7, g); }
    }
}

// V = U * RX(ang): fuse the per-sample RX into the FOLLOWING fixed gate
__device__ __forceinline__ void buildV(float v[8], const float* u, float ang) {
    float s, c;
    __sincosf(ang, &s, &c);
    v[0] = c * u[0] + s * u[3];  v[1] = c * u[1] - s * u[2];
    v[2] = s * u[1] + c * u[2];  v[3] = c * u[3] - s * u[0];
    v[4] = c * u[4] + s * u[7];  v[5] = c * u[5] - s * u[6];
    v[6] = s * u[5] + c * u[6];  v[7] = c * u[7] - s * u[4];
}

__device__ __forceinline__ float parity_exp(const ull* R, const ull* I) {
    // slot popcount even {0,3,5,6}: lane parity (+,-); odd {1,2,4,7}: (-,+)
    ull accA = 0, accB = 0;
#pragma unroll
    for (int k = 0; k < 8; k++) {
        bool even = (k == 0 || k == 3 || k == 5 || k == 6);
        if (even) { accA = fma2(R[k], R[k], accA); accA = fma2(I[k], I[k], accA); }
        else      { accB = fma2(R[k], R[k], accB); accB = fma2(I[k], I[k], accB); }
    }
    float aL, aH, bL, bH;
    up2(accA, aL, aH); up2(accB, bL, bH);
    return (aL - aH) - (bL - bH);
}

__global__ __launch_bounds__(128)
void pqc_kernel(const float4* __restrict__ x,
                const float* __restrict__ lmbd,
                float* __restrict__ out, int B2) {
    __shared__ float sh_g[NGATES * 8];
    __shared__ float sh_l[NL * NQ];
    for (int i = threadIdx.x; i < NGATES * 8; i += blockDim.x) sh_g[i] = g_gates[i];
    for (int i = threadIdx.x; i < NL * NQ; i += blockDim.x) sh_l[i] = 0.5f * lmbd[i];
    __syncthreads();

    int t = blockIdx.x * blockDim.x + threadIdx.x;
    if (t >= B2) return;

    float4 xa = x[t];
    float4 xb = x[t + B2];
    float xqa[NQ] = {xa.x, xa.y, xa.z, xa.w};
    float xqb[NQ] = {xb.x, xb.y, xb.z, xb.w};

    ull RA[8], IA[8], RB[8], IB[8];

    // ---- layer-0 fixed gates on |0000>: tensor product (sample-independent) ----
    {
        float q1r[2], q1i[2], q2r[2], q2i[2], q3r[2], q3i[2];
        q1r[0] = sh_g[8 + 0];  q1i[0] = sh_g[8 + 1];  q1r[1] = sh_g[8 + 4];  q1i[1] = sh_g[8 + 5];
        q2r[0] = sh_g[16 + 0]; q2i[0] = sh_g[16 + 1]; q2r[1] = sh_g[16 + 4]; q2i[1] = sh_g[16 + 5];
        q3r[0] = sh_g[24 + 0]; q3i[0] = sh_g[24 + 1]; q3r[1] = sh_g[24 + 4]; q3i[1] = sh_g[24 + 5];
        float a0r = sh_g[0], a0i = sh_g[1], a1r = sh_g[4], a1i = sh_g[5];
        ull Apr = pk2(a0r, a1r), Api = pk2(a0i, a1i), nApi = pk2(-a0i, -a1i);
        float wr[4], wi[4];
#pragma unroll
        for (int b2 = 0; b2 < 2; b2++)
#pragma unroll
            for (int b3 = 0; b3 < 2; b3++) {
                wr[b2 * 2 + b3] = q2r[b2] * q3r[b3] - q2i[b2] * q3i[b3];
                wi[b2 * 2 + b3] = q2r[b2] * q3i[b3] + q2i[b2] * q3r[b3];
            }
#pragma unroll
        for (int k = 0; k < 8; k++) {
            int b1 = k >> 2, w = k & 3;
            float vr = q1r[b1] * wr[w] - q1i[b1] * wi[w];
            float vi = q1r[b1] * wi[w] + q1i[b1] * wr[w];
            ull vbr = bc2(vr), vbi = bc2(vi);
            RA[k] = fma2(nApi, vbi, mul2(Apr, vbr));
            IA[k] = fma2(Api, vbr, mul2(Apr, vbi));
            RB[k] = RA[k]; IB[k] = IA[k];
        }
    }

    // CZ sign masks on packed lanes (b0=0 lo, b0=1 hi)
    const ull PN = 0xBF8000003F800000ULL;  // (+1, -1)
    const ull NP = 0x3F800000BF800000ULL;  // (-1, +1)

    // Loop l=0..NL-1 covers: CZ_l, then V = U(l+1)*RX_l. The l=NL-1 iteration
    // consumes the final fixed layer U(NL) — NO epilogue after this loop.
    for (int l = 0; l < NL; l++) {
        RA[1] = mul2(RA[1], PN); IA[1] = mul2(IA[1], PN);
        RA[4] = mul2(RA[4], PN); IA[4] = mul2(IA[4], PN);
        RA[3] = mul2(RA[3], NP); IA[3] = mul2(IA[3], NP);
        RA[6] = mul2(RA[6], NP); IA[6] = mul2(IA[6], NP);
        RB[1] = mul2(RB[1], PN); IB[1] = mul2(IB[1], PN);
        RB[4] = mul2(RB[4], PN); IB[4] = mul2(IB[4], PN);
        RB[3] = mul2(RB[3], NP); IB[3] = mul2(IB[3], NP);
        RB[6] = mul2(RB[6], NP); IB[6] = mul2(IB[6], NP);

        const float* gl = &sh_g[(l + 1) * NQ * 8];
        const float* ll = &sh_l[l * NQ];

#pragma unroll
        for (int q = 0; q < NQ; q++) {
            float u[8];
#pragma unroll
            for (int i = 0; i < 8; i++) u[i] = gl[q * 8 + i];
            float lq = ll[q];
            float va[8], vb[8];
            buildV(va, u, lq * xqa[q]);
            buildV(vb, u, lq * xqb[q]);
            if (q == 0)      { apply_q<0>(RA, IA, va); apply_q<0>(RB, IB, vb); }
            else if (q == 1) { apply_q<1>(RA, IA, va); apply_q<1>(RB, IB, vb); }
            else if (q == 2) { apply_q<2>(RA, IA, va); apply_q<2>(RB, IB, vb); }
            else             { apply_q<3>(RA, IA, va); apply_q<3>(RB, IB, vb); }
        }
    }

    out[t] = parity_exp(RA, IA);
    out[t + B2] = parity_exp(RB, IB);
}

extern "C" void kernel_launch(void* const* d_in, const int* in_sizes, int n_in,
                              void* d_out, int out_size) {
    const float* x     = (const float*)d_in[0];   // [B, 4]
    const float* theta = (const float*)d_in[1];   // [1, 108]
    const float* lmbd  = (const float*)d_in[2];   // [32]
    float* out = (float*)d_out;                   // [B, 1]
    int B = in_sizes[0] / NQ;
    int B2 = B / 2;

    precompute_gates_kernel<<<1, 64>>>(theta);
    int threads = 128;
    int blocks = (B2 + threads - 1) / threads;
    pqc_kernel<<<blocks, threads>>>((const float4*)x, lmbd, out, B2);
}